// round 4
// baseline (speedup 1.0000x reference)
#include <cuda_runtime.h>
#include <cuda_bf16.h>
#include <stdint.h>

// Scatter-add F_st[e] * edge_vec[e] into out[edge_idx[e]], n_atoms x 3.
//
// R3 design:
//  - All edge-data loads go through cp.async.bulk (bulk copy engine -> smem,
//    double-buffered with mbarriers). This removes ALL load wavefronts from the
//    L1tex per-lane pipe, which is then dedicated to the 6.4M scattered
//    RED.128 lanes (the irreducible cost of this scatter).
//  - g_acc is 16B-padded so each edge is ONE red.global.add.v4.f32.
//  - copy_zero4 compacts [n,4]->[n,3] with 4 atoms/thread (MLP=4, all 16B ops)
//    and resets g_acc, preserving the zero-on-entry invariant.

#define MAX_ATOMS 100000
#define TILE      1024      // edges per pipeline stage
#define STAGES    2
#define TPB       256

__device__ float4 g_acc[MAX_ATOMS];

__device__ __forceinline__ void red_add_v4(float4* p, float x, float y, float z) {
    asm volatile("red.global.add.v4.f32 [%0], {%1, %2, %3, %4};"
                 :: "l"(p), "f"(x), "f"(y), "f"(z), "f"(0.0f) : "memory");
}

__device__ __forceinline__ uint32_t smem_u32(const void* p) {
    return (uint32_t)__cvta_generic_to_shared(p);
}

__device__ __forceinline__ void mbar_init(uint32_t m, uint32_t count) {
    asm volatile("mbarrier.init.shared.b64 [%0], %1;" :: "r"(m), "r"(count) : "memory");
}

__device__ __forceinline__ void mbar_wait(uint32_t m, uint32_t phase) {
    asm volatile(
        "{\n\t"
        ".reg .pred P;\n\t"
        "WAIT_%=:\n\t"
        "mbarrier.try_wait.parity.shared.b64 P, [%0], %1;\n\t"
        "@!P bra WAIT_%=;\n\t"
        "}"
        :: "r"(m), "r"(phase) : "memory");
}

__device__ __forceinline__ void bulk_g2s(uint32_t dst, const void* src,
                                         uint32_t bytes, uint32_t mbar) {
    asm volatile(
        "cp.async.bulk.shared::cluster.global.mbarrier::complete_tx::bytes "
        "[%0], [%1], %2, [%3];"
        :: "r"(dst), "l"(src), "r"(bytes), "r"(mbar) : "memory");
}

struct __align__(128) Stage {
    float f[TILE];       // 4 KB
    float v[TILE * 3];   // 12 KB
    int   idx[TILE];     // 4 KB
};

__global__ __launch_bounds__(TPB)
void scatter_tma(const float* __restrict__ F,
                 const float* __restrict__ V,
                 const int*   __restrict__ I,
                 int n_tiles, int n_edges, int n_atoms) {
    __shared__ Stage st[STAGES];
    __shared__ __align__(8) unsigned long long mbar[STAGES];

    const int tid = threadIdx.x;

    if (tid == 0) {
        for (int s = 0; s < STAGES; s++) mbar_init(smem_u32(&mbar[s]), 1);
    }
    __syncthreads();

    // Tiles for this block: t_k = blockIdx.x + k * gridDim.x, k = 0..K-1
    int K = 0;
    if ((int)blockIdx.x < n_tiles)
        K = (n_tiles - 1 - (int)blockIdx.x) / (int)gridDim.x + 1;

    const uint32_t STAGE_BYTES = TILE * 4u + TILE * 12u + TILE * 4u;  // 20480

    // Prologue: fill the pipeline.
    if (tid == 0) {
        for (int s = 0; s < STAGES && s < K; s++) {
            size_t tile = (size_t)blockIdx.x + (size_t)s * gridDim.x;
            uint32_t m = smem_u32(&mbar[s]);
            asm volatile("mbarrier.arrive.expect_tx.shared.b64 _, [%0], %1;"
                         :: "r"(m), "r"(STAGE_BYTES) : "memory");
            bulk_g2s(smem_u32(st[s].f),   F + tile * TILE,     TILE * 4u,  m);
            bulk_g2s(smem_u32(st[s].v),   V + tile * TILE * 3, TILE * 12u, m);
            bulk_g2s(smem_u32(st[s].idx), I + tile * TILE,     TILE * 4u,  m);
        }
    }

    int ph0 = 0, ph1 = 0;  // per-stage phase parity

    for (int k = 0; k < K; k++) {
        int s = k & 1;
        uint32_t m = smem_u32(&mbar[s]);
        if (s == 0) { mbar_wait(m, ph0); ph0 ^= 1; }
        else        { mbar_wait(m, ph1); ph1 ^= 1; }

        // Consume: thread tid handles edges [4*tid, 4*tid+4) of this tile.
        float4 f  = reinterpret_cast<const float4*>(st[s].f)[tid];
        int4   id = reinterpret_cast<const int4*>(st[s].idx)[tid];
        const float4* vv = reinterpret_cast<const float4*>(st[s].v);
        float4 a = vv[3 * tid + 0];   // 48B-stride LDS.128: bank-conflict-free
        float4 b = vv[3 * tid + 1];
        float4 c = vv[3 * tid + 2];

        // e0=(a.x,a.y,a.z) e1=(a.w,b.x,b.y) e2=(b.z,b.w,c.x) e3=(c.y,c.z,c.w)
        if ((unsigned)id.x < (unsigned)n_atoms)
            red_add_v4(&g_acc[id.x], f.x * a.x, f.x * a.y, f.x * a.z);
        if ((unsigned)id.y < (unsigned)n_atoms)
            red_add_v4(&g_acc[id.y], f.y * a.w, f.y * b.x, f.y * b.y);
        if ((unsigned)id.z < (unsigned)n_atoms)
            red_add_v4(&g_acc[id.z], f.z * b.z, f.z * b.w, f.z * c.x);
        if ((unsigned)id.w < (unsigned)n_atoms)
            red_add_v4(&g_acc[id.w], f.w * c.y, f.w * c.z, f.w * c.w);

        __syncthreads();  // all readers done before this stage is re-armed

        if (tid == 0 && k + STAGES < K) {
            size_t tile = (size_t)blockIdx.x + (size_t)(k + STAGES) * gridDim.x;
            asm volatile("mbarrier.arrive.expect_tx.shared.b64 _, [%0], %1;"
                         :: "r"(m), "r"(STAGE_BYTES) : "memory");
            bulk_g2s(smem_u32(st[s].f),   F + tile * TILE,     TILE * 4u,  m);
            bulk_g2s(smem_u32(st[s].v),   V + tile * TILE * 3, TILE * 12u, m);
            bulk_g2s(smem_u32(st[s].idx), I + tile * TILE,     TILE * 4u,  m);
        }
    }

    // Tail: edges beyond the last full tile (block 0 only, direct LDG path).
    if (blockIdx.x == 0) {
        for (int e = n_tiles * TILE + tid; e < n_edges; e += TPB) {
            float fe = F[e];
            int   i  = I[e];
            if ((unsigned)i < (unsigned)n_atoms)
                red_add_v4(&g_acc[i], fe * V[3 * e + 0], fe * V[3 * e + 1],
                           fe * V[3 * e + 2]);
        }
    }
}

// Compact [n,4] -> [n,3] into d_out AND reset the accumulator.
// 4 atoms per thread: 4 independent LDG.128 (MLP=4), 4 STG.128 zeros,
// 3 packed STG.128 outputs.
__global__ __launch_bounds__(TPB)
void copy_zero4(float4* __restrict__ out4, int n_atoms) {
    int m = blockIdx.x * blockDim.x + threadIdx.x;
    int a = 4 * m;
    if (a + 3 < n_atoms) {
        float4 v0 = g_acc[a + 0];
        float4 v1 = g_acc[a + 1];
        float4 v2 = g_acc[a + 2];
        float4 v3 = g_acc[a + 3];
        float4 z = make_float4(0.f, 0.f, 0.f, 0.f);
        g_acc[a + 0] = z; g_acc[a + 1] = z; g_acc[a + 2] = z; g_acc[a + 3] = z;
        out4[3 * m + 0] = make_float4(v0.x, v0.y, v0.z, v1.x);
        out4[3 * m + 1] = make_float4(v1.y, v1.z, v2.x, v2.y);
        out4[3 * m + 2] = make_float4(v2.z, v3.x, v3.y, v3.z);
    } else if (a < n_atoms) {
        // scalar tail for n_atoms % 4 != 0
        float* out = reinterpret_cast<float*>(out4);
        for (int i = a; i < n_atoms; i++) {
            float4 v = g_acc[i];
            g_acc[i] = make_float4(0.f, 0.f, 0.f, 0.f);
            out[3 * i + 0] = v.x;
            out[3 * i + 1] = v.y;
            out[3 * i + 2] = v.z;
        }
    }
}

extern "C" void kernel_launch(void* const* d_in, const int* in_sizes, int n_in,
                              void* d_out, int out_size) {
    const float* F = (const float*)d_in[0];   // F_st     [E,1] f32
    const float* V = (const float*)d_in[1];   // edge_vec [E,3] f32
    const int*   I = (const int*)d_in[2];     // edge_idx [E]   i32
    float4* out4 = (float4*)d_out;            // [n_atoms,3] f32 (16B-aligned base)

    int n_edges = in_sizes[0];
    int n_atoms = out_size / 3;
    if (n_atoms > MAX_ATOMS) n_atoms = MAX_ATOMS;

    int n_tiles = n_edges / TILE;

    int grid = 148 * 5;                 // 5 blocks/SM by smem (41 KB/block)
    if (grid > n_tiles && n_tiles > 0) grid = n_tiles;
    if (grid < 1) grid = 1;

    scatter_tma<<<grid, TPB>>>(F, V, I, n_tiles, n_edges, n_atoms);

    int groups = (n_atoms + 3) / 4;
    copy_zero4<<<(groups + TPB - 1) / TPB, TPB>>>(out4, n_atoms);
}

// round 5
// speedup vs baseline: 1.0422x; 1.0422x over previous
#include <cuda_runtime.h>
#include <cuda_bf16.h>
#include <stdint.h>

// Scatter-add F_st[e] * edge_vec[e] into out[edge_idx[e]], n_atoms x 3.
//
// Established by R1-R3 measurements: the scatter is bound by RED lane
// throughput (6.4M scattered red.global.add.v4.f32 lanes, ~43us); load-path
// engineering (smem staging R2, TMA pipeline R3) is neutral-to-negative.
// So: simplest fully-parallel scatter (R1 shape) + a latency-optimized
// copy&zero epilogue (1 atom/thread, max parallelism; g_acc is L2-resident).
//
// g_acc is a 16B-padded accumulator (one vec4 RED per edge instead of 3
// scalar REDs). copy_zero compacts [n,4]->[n,3] into d_out AND resets g_acc,
// maintaining the zero-on-entry invariant (device globals start zeroed).

#define MAX_ATOMS 100000

__device__ float4 g_acc[MAX_ATOMS];

__device__ __forceinline__ void red_add_v4(float4* p, float x, float y, float z) {
    asm volatile("red.global.add.v4.f32 [%0], {%1, %2, %3, %4};"
                 :: "l"(p), "f"(x), "f"(y), "f"(z), "f"(0.0f) : "memory");
}

// 4 edges per thread, all loads LDG.128, fully parallel grid.
__global__ __launch_bounds__(256)
void scatter_kernel(const float4* __restrict__ F4,
                    const float4* __restrict__ V4,
                    const int4*   __restrict__ I4,
                    int nq, int n_edges, int n_atoms) {
    int t = blockIdx.x * blockDim.x + threadIdx.x;
    if (t < nq) {
        float4 f  = F4[t];
        float4 a  = V4[3 * t + 0];
        float4 b  = V4[3 * t + 1];
        float4 c  = V4[3 * t + 2];
        int4   id = I4[t];

        // e0=(a.x,a.y,a.z) e1=(a.w,b.x,b.y) e2=(b.z,b.w,c.x) e3=(c.y,c.z,c.w)
        if ((unsigned)id.x < (unsigned)n_atoms)
            red_add_v4(&g_acc[id.x], f.x * a.x, f.x * a.y, f.x * a.z);
        if ((unsigned)id.y < (unsigned)n_atoms)
            red_add_v4(&g_acc[id.y], f.y * a.w, f.y * b.x, f.y * b.y);
        if ((unsigned)id.z < (unsigned)n_atoms)
            red_add_v4(&g_acc[id.z], f.z * b.z, f.z * b.w, f.z * c.x);
        if ((unsigned)id.w < (unsigned)n_atoms)
            red_add_v4(&g_acc[id.w], f.w * c.y, f.w * c.z, f.w * c.w);
    } else if (t == nq) {
        // scalar tail (n_edges % 4 edges), exactly one thread
        const float* F   = (const float*)F4;
        const float* V   = (const float*)V4;
        const int*   IDX = (const int*)I4;
        for (int e = 4 * nq; e < n_edges; e++) {
            float fe = F[e];
            int   i  = IDX[e];
            if ((unsigned)i < (unsigned)n_atoms)
                red_add_v4(&g_acc[i], fe * V[3 * e + 0], fe * V[3 * e + 1],
                           fe * V[3 * e + 2]);
        }
    }
}

// 1 atom per thread: one L2-hit LDG.128, one STG.128 zero-reset, three STG.32
// outputs. Latency hidden by thread-level parallelism (100k threads).
__global__ __launch_bounds__(256)
void copy_zero(float* __restrict__ out, int n_atoms) {
    int i = blockIdx.x * blockDim.x + threadIdx.x;
    if (i < n_atoms) {
        float4 v = g_acc[i];
        g_acc[i] = make_float4(0.f, 0.f, 0.f, 0.f);
        out[3 * i + 0] = v.x;
        out[3 * i + 1] = v.y;
        out[3 * i + 2] = v.z;
    }
}

extern "C" void kernel_launch(void* const* d_in, const int* in_sizes, int n_in,
                              void* d_out, int out_size) {
    const float4* F4 = (const float4*)d_in[0];   // F_st     [E,1] f32
    const float4* V4 = (const float4*)d_in[1];   // edge_vec [E,3] f32
    const int4*   I4 = (const int4*)d_in[2];     // edge_idx [E]   i32
    float* out = (float*)d_out;                  // [n_atoms,3] f32

    int n_edges = in_sizes[0];
    int n_atoms = out_size / 3;
    if (n_atoms > MAX_ATOMS) n_atoms = MAX_ATOMS;

    int nq = n_edges / 4;

    const int TB = 256;
    // nq+1 threads: the extra thread handles the scalar tail
    scatter_kernel<<<(nq + 1 + TB - 1) / TB, TB>>>(F4, V4, I4, nq, n_edges, n_atoms);
    copy_zero<<<(n_atoms + TB - 1) / TB, TB>>>(out, n_atoms);
}

// round 6
// speedup vs baseline: 1.1170x; 1.0718x over previous
#include <cuda_runtime.h>
#include <cuda_bf16.h>
#include <stdint.h>

// Scatter-add F_st[e] * edge_vec[e] into out[edge_idx[e]], n_atoms x 3.
//
// Measured across R1-R4: the scatter is pinned at ~43-45us by RED lane
// throughput (6.4M scattered red.global.add.v4.f32); load-path engineering is
// neutral-to-negative. The epilogue was the swing item (up to 8.2us): at
// 1 atom/thread a 100k-thread grid can't fill 148 SMs (occ 21.9%) and each
// thread is a dependent LDG->STG chain.
//
// R5: keep R1 scatter; epilogue at ONE 4B element per thread (400k threads,
// fully independent ops, full occupancy, TLP-hidden L2 latency).
//
// g_acc is a 16B-padded accumulator (one vec4 RED per edge instead of 3
// scalar REDs). The epilogue compacts [n,4]->[n,3] into d_out AND resets
// g_acc, maintaining the zero-on-entry invariant (device globals start zeroed).

#define MAX_ATOMS 100000

__device__ float4 g_acc[MAX_ATOMS];

__device__ __forceinline__ void red_add_v4(float4* p, float x, float y, float z) {
    asm volatile("red.global.add.v4.f32 [%0], {%1, %2, %3, %4};"
                 :: "l"(p), "f"(x), "f"(y), "f"(z), "f"(0.0f) : "memory");
}

// 4 edges per thread, all loads LDG.128, fully parallel grid. (R1 shape.)
__global__ __launch_bounds__(256)
void scatter_kernel(const float4* __restrict__ F4,
                    const float4* __restrict__ V4,
                    const int4*   __restrict__ I4,
                    int nq, int n_edges, int n_atoms) {
    int t = blockIdx.x * blockDim.x + threadIdx.x;
    if (t < nq) {
        float4 f  = F4[t];
        float4 a  = V4[3 * t + 0];
        float4 b  = V4[3 * t + 1];
        float4 c  = V4[3 * t + 2];
        int4   id = I4[t];

        // e0=(a.x,a.y,a.z) e1=(a.w,b.x,b.y) e2=(b.z,b.w,c.x) e3=(c.y,c.z,c.w)
        if ((unsigned)id.x < (unsigned)n_atoms)
            red_add_v4(&g_acc[id.x], f.x * a.x, f.x * a.y, f.x * a.z);
        if ((unsigned)id.y < (unsigned)n_atoms)
            red_add_v4(&g_acc[id.y], f.y * a.w, f.y * b.x, f.y * b.y);
        if ((unsigned)id.z < (unsigned)n_atoms)
            red_add_v4(&g_acc[id.z], f.z * b.z, f.z * b.w, f.z * c.x);
        if ((unsigned)id.w < (unsigned)n_atoms)
            red_add_v4(&g_acc[id.w], f.w * c.y, f.w * c.z, f.w * c.w);
    } else if (t == nq) {
        // scalar tail (n_edges % 4 edges), exactly one thread
        const float* F   = (const float*)F4;
        const float* V   = (const float*)V4;
        const int*   IDX = (const int*)I4;
        for (int e = 4 * nq; e < n_edges; e++) {
            float fe = F[e];
            int   i  = IDX[e];
            if ((unsigned)i < (unsigned)n_atoms)
                red_add_v4(&g_acc[i], fe * V[3 * e + 0], fe * V[3 * e + 1],
                           fe * V[3 * e + 2]);
        }
    }
}

// One 4B element per thread. Threads [0,3n): copy acc component -> out and
// zero it. Threads [3n,4n): zero the unused w component. Every acc address is
// owned by exactly one thread (no races); per-thread WAR (load then zero-store
// to same address) is ordered by program order.
__global__ __launch_bounds__(256)
void copy_zero_fine(float* __restrict__ out, int n_atoms) {
    float* acc = reinterpret_cast<float*>(g_acc);
    int i = blockIdx.x * blockDim.x + threadIdx.x;
    int n3 = 3 * n_atoms;
    if (i < n3) {
        int atom = i / 3;
        int comp = i - 3 * atom;
        int ai = 4 * atom + comp;
        float v = acc[ai];
        out[i] = v;
        acc[ai] = 0.0f;
    } else {
        int j = i - n3;               // [0, n_atoms): w components
        if (j < n_atoms) acc[4 * j + 3] = 0.0f;
    }
}

extern "C" void kernel_launch(void* const* d_in, const int* in_sizes, int n_in,
                              void* d_out, int out_size) {
    const float4* F4 = (const float4*)d_in[0];   // F_st     [E,1] f32
    const float4* V4 = (const float4*)d_in[1];   // edge_vec [E,3] f32
    const int4*   I4 = (const int4*)d_in[2];     // edge_idx [E]   i32
    float* out = (float*)d_out;                  // [n_atoms,3] f32

    int n_edges = in_sizes[0];
    int n_atoms = out_size / 3;
    if (n_atoms > MAX_ATOMS) n_atoms = MAX_ATOMS;

    int nq = n_edges / 4;

    const int TB = 256;
    // nq+1 threads: the extra thread handles the scalar tail
    scatter_kernel<<<(nq + 1 + TB - 1) / TB, TB>>>(F4, V4, I4, nq, n_edges, n_atoms);

    int total = 4 * n_atoms;                     // 3n copy threads + n zero-w threads
    copy_zero_fine<<<(total + TB - 1) / TB, TB>>>(out, n_atoms);
}